// round 10
// baseline (speedup 1.0000x reference)
#include <cuda_runtime.h>

// Work in log2 units; clamp -100 (nat log) = -100/ln2 in log2 units.
#define LG2_CLAMP (-144.26950408889634f)
#define LN2       (0.6931471805599453f)

// Cross-replay scratch: last block resets both to 0, so every graph replay
// starts from a clean state (initial static value is 0).
__device__ float        g_acc   = 0.0f;
__device__ unsigned int g_count = 0u;

__device__ __forceinline__ float lg2_fast(float x) {
    float r;
    asm("lg2.approx.f32 %0, %1;" : "=f"(r) : "f"(x));
    return r;
}

__device__ __forceinline__ float4 ldcs4(const float4* p) {
    float4 v;
    asm volatile("ld.global.cs.v4.f32 {%0,%1,%2,%3}, [%4];"
                 : "=f"(v.x), "=f"(v.y), "=f"(v.z), "=f"(v.w)
                 : "l"(p));
    return v;
}

__device__ __forceinline__ float bce4_lg2(float4 p, float4 t) {
    float lp0 = fmaxf(lg2_fast(p.x),        LG2_CLAMP);
    float lq0 = fmaxf(lg2_fast(1.0f - p.x), LG2_CLAMP);
    float lp1 = fmaxf(lg2_fast(p.y),        LG2_CLAMP);
    float lq1 = fmaxf(lg2_fast(1.0f - p.y), LG2_CLAMP);
    float lp2 = fmaxf(lg2_fast(p.z),        LG2_CLAMP);
    float lq2 = fmaxf(lg2_fast(1.0f - p.z), LG2_CLAMP);
    float lp3 = fmaxf(lg2_fast(p.w),        LG2_CLAMP);
    float lq3 = fmaxf(lg2_fast(1.0f - p.w), LG2_CLAMP);
    float s = lq0 + t.x * (lp0 - lq0);
    s += lq1 + t.y * (lp1 - lq1);
    s += lq2 + t.z * (lp2 - lq2);
    s += lq3 + t.w * (lp3 - lq3);
    return s;
}

#define UNROLL 8

__global__ void __launch_bounds__(256)
vloss_main(const float* __restrict__ pred,
           const float* __restrict__ tru,
           float* __restrict__ out,
           int n4, float inv_scale) {
    const float4* p4 = reinterpret_cast<const float4*>(pred);
    const float4* t4 = reinterpret_cast<const float4*>(tru);

    float acc = 0.0f;
    const int tid    = blockIdx.x * blockDim.x + threadIdx.x;
    const int stride = gridDim.x * blockDim.x;

    // Unrolled-by-8 main loop: 16 independent LDG.128 front-batched per
    // thread (~8KB per warp in flight; M_max ~55/warp so well under cap).
    int i = tid;
    const int strideU = stride * UNROLL;
    for (; i + (UNROLL - 1) * stride < n4; i += strideU) {
        float4 p[UNROLL], t[UNROLL];
        #pragma unroll
        for (int u = 0; u < UNROLL; u++) p[u] = ldcs4(p4 + i + u * stride);
        #pragma unroll
        for (int u = 0; u < UNROLL; u++) t[u] = ldcs4(t4 + i + u * stride);
        #pragma unroll
        for (int u = 0; u < UNROLL; u++) acc -= bce4_lg2(p[u], t[u]);
    }
    // Remainder
    for (; i < n4; i += stride) {
        float4 p = ldcs4(p4 + i);
        float4 t = ldcs4(t4 + i);
        acc -= bce4_lg2(p, t);
    }

    // warp reduce
    #pragma unroll
    for (int off = 16; off > 0; off >>= 1)
        acc += __shfl_down_sync(0xFFFFFFFFu, acc, off);

    __shared__ float warp_sums[8];
    int lane = threadIdx.x & 31;
    int wid  = threadIdx.x >> 5;
    if (lane == 0) warp_sums[wid] = acc;
    __syncthreads();

    if (wid == 0 && lane == 0) {
        float v = 0.0f;
        #pragma unroll
        for (int w = 0; w < 8; w++) v += warp_sums[w];

        // Accumulate block partial into device-global scalar.
        atomicAdd(&g_acc, v);
        __threadfence();

        // Ticket: last block finalizes the output and resets state so the
        // next graph replay starts clean.
        unsigned int ticket = atomicAdd(&g_count, 1u);
        if (ticket == gridDim.x - 1) {
            *out = g_acc * inv_scale;
            g_acc   = 0.0f;
            g_count = 0u;
        }
    }
}

extern "C" void kernel_launch(void* const* d_in, const int* in_sizes, int n_in,
                              void* d_out, int out_size) {
    const float* pred = (const float*)d_in[0];
    const float* tru  = (const float*)d_in[1];
    float* out = (float*)d_out;

    int n = in_sizes[0];               // 33,554,432
    int n4 = n >> 2;
    // divisor: H * B = 65536 * 64; multiply by ln2 to convert log2 -> ln
    float inv_scale = LN2 / (65536.0f * 64.0f);

    int threads = 256;
    int blocks = 148 * 16;             // 2368 blocks: measured-best concurrency
    vloss_main<<<blocks, threads>>>(pred, tru, out, n4, inv_scale);
}

// round 11
// speedup vs baseline: 1.0128x; 1.0128x over previous
#include <cuda_runtime.h>

// Work in log2 units; clamp -100 (nat log) = -100/ln2 in log2 units.
#define LG2_CLAMP (-144.26950408889634f)
#define LN2       (0.6931471805599453f)

// Cross-replay scratch: last block resets both to 0, so every graph replay
// starts from a clean state (initial static value is 0).
__device__ float        g_acc   = 0.0f;
__device__ unsigned int g_count = 0u;

__device__ __forceinline__ float lg2_fast(float x) {
    float r;
    asm("lg2.approx.f32 %0, %1;" : "=f"(r) : "f"(x));
    return r;
}

__device__ __forceinline__ float4 ldcs4(const float4* p) {
    float4 v;
    asm volatile("ld.global.cs.v4.f32 {%0,%1,%2,%3}, [%4];"
                 : "=f"(v.x), "=f"(v.y), "=f"(v.z), "=f"(v.w)
                 : "l"(p));
    return v;
}

__device__ __forceinline__ float bce4_lg2(float4 p, float4 t) {
    float lp0 = fmaxf(lg2_fast(p.x),        LG2_CLAMP);
    float lq0 = fmaxf(lg2_fast(1.0f - p.x), LG2_CLAMP);
    float lp1 = fmaxf(lg2_fast(p.y),        LG2_CLAMP);
    float lq1 = fmaxf(lg2_fast(1.0f - p.y), LG2_CLAMP);
    float lp2 = fmaxf(lg2_fast(p.z),        LG2_CLAMP);
    float lq2 = fmaxf(lg2_fast(1.0f - p.z), LG2_CLAMP);
    float lp3 = fmaxf(lg2_fast(p.w),        LG2_CLAMP);
    float lq3 = fmaxf(lg2_fast(1.0f - p.w), LG2_CLAMP);
    float s = lq0 + t.x * (lp0 - lq0);
    s += lq1 + t.y * (lp1 - lq1);
    s += lq2 + t.z * (lp2 - lq2);
    s += lq3 + t.w * (lp3 - lq3);
    return s;
}

__global__ void __launch_bounds__(256)
vloss_main(const float* __restrict__ pred,
           const float* __restrict__ tru,
           float* __restrict__ out,
           int n4, float inv_scale) {
    const float4* p4 = reinterpret_cast<const float4*>(pred);
    const float4* t4 = reinterpret_cast<const float4*>(tru);

    float acc = 0.0f;
    const int tid    = blockIdx.x * blockDim.x + threadIdx.x;
    const int stride = gridDim.x * blockDim.x;

    // Unrolled-by-4 main loop: 8 independent LDG.128 front-batched per iter.
    int i = tid;
    const int stride4 = stride * 4;
    for (; i + 3 * stride < n4; i += stride4) {
        float4 pa = ldcs4(p4 + i);
        float4 pb = ldcs4(p4 + i + stride);
        float4 pc = ldcs4(p4 + i + 2 * stride);
        float4 pd = ldcs4(p4 + i + 3 * stride);
        float4 ta = ldcs4(t4 + i);
        float4 tb = ldcs4(t4 + i + stride);
        float4 tc = ldcs4(t4 + i + 2 * stride);
        float4 td = ldcs4(t4 + i + 3 * stride);

        acc -= bce4_lg2(pa, ta);
        acc -= bce4_lg2(pb, tb);
        acc -= bce4_lg2(pc, tc);
        acc -= bce4_lg2(pd, td);
    }
    // Remainder
    for (; i < n4; i += stride) {
        float4 p = ldcs4(p4 + i);
        float4 t = ldcs4(t4 + i);
        acc -= bce4_lg2(p, t);
    }

    // warp reduce
    #pragma unroll
    for (int off = 16; off > 0; off >>= 1)
        acc += __shfl_down_sync(0xFFFFFFFFu, acc, off);

    __shared__ float warp_sums[8];
    int lane = threadIdx.x & 31;
    int wid  = threadIdx.x >> 5;
    if (lane == 0) warp_sums[wid] = acc;
    __syncthreads();

    if (wid == 0 && lane == 0) {
        float v = 0.0f;
        #pragma unroll
        for (int w = 0; w < 8; w++) v += warp_sums[w];

        // Accumulate block partial into device-global scalar.
        atomicAdd(&g_acc, v);
        __threadfence();

        // Ticket: last block finalizes the output and resets state so the
        // next graph replay starts clean.
        unsigned int ticket = atomicAdd(&g_count, 1u);
        if (ticket == gridDim.x - 1) {
            *out = g_acc * inv_scale;
            g_acc   = 0.0f;
            g_count = 0u;
        }
    }
}

extern "C" void kernel_launch(void* const* d_in, const int* in_sizes, int n_in,
                              void* d_out, int out_size) {
    const float* pred = (const float*)d_in[0];
    const float* tru  = (const float*)d_in[1];
    float* out = (float*)d_out;

    int n = in_sizes[0];               // 33,554,432
    int n4 = n >> 2;
    // divisor: H * B = 65536 * 64; multiply by ln2 to convert log2 -> ln
    float inv_scale = LN2 / (65536.0f * 64.0f);

    int threads = 256;
    int blocks = 148 * 16;             // 2368 blocks: measured-best concurrency
    vloss_main<<<blocks, threads>>>(pred, tru, out, n4, inv_scale);
}

// round 12
// speedup vs baseline: 1.0471x; 1.0338x over previous
#include <cuda_runtime.h>

// Work in log2 units; clamp -100 (nat log) = -100/ln2 in log2 units.
#define LG2_CLAMP (-144.26950408889634f)
#define LN2       (0.6931471805599453f)

// Cross-replay scratch: last block resets both to 0, so every graph replay
// starts from a clean state (initial static value is 0).
__device__ float        g_acc   = 0.0f;
__device__ unsigned int g_count = 0u;

__device__ __forceinline__ float lg2_fast(float x) {
    float r;
    asm("lg2.approx.f32 %0, %1;" : "=f"(r) : "f"(x));
    return r;
}

// Default-policy 128-bit load (no evict-first hint — isolating the .cs variable).
__device__ __forceinline__ float4 ld4(const float4* p) {
    float4 v;
    asm volatile("ld.global.v4.f32 {%0,%1,%2,%3}, [%4];"
                 : "=f"(v.x), "=f"(v.y), "=f"(v.z), "=f"(v.w)
                 : "l"(p));
    return v;
}

__device__ __forceinline__ float bce4_lg2(float4 p, float4 t) {
    float lp0 = fmaxf(lg2_fast(p.x),        LG2_CLAMP);
    float lq0 = fmaxf(lg2_fast(1.0f - p.x), LG2_CLAMP);
    float lp1 = fmaxf(lg2_fast(p.y),        LG2_CLAMP);
    float lq1 = fmaxf(lg2_fast(1.0f - p.y), LG2_CLAMP);
    float lp2 = fmaxf(lg2_fast(p.z),        LG2_CLAMP);
    float lq2 = fmaxf(lg2_fast(1.0f - p.z), LG2_CLAMP);
    float lp3 = fmaxf(lg2_fast(p.w),        LG2_CLAMP);
    float lq3 = fmaxf(lg2_fast(1.0f - p.w), LG2_CLAMP);
    float s = lq0 + t.x * (lp0 - lq0);
    s += lq1 + t.y * (lp1 - lq1);
    s += lq2 + t.z * (lp2 - lq2);
    s += lq3 + t.w * (lp3 - lq3);
    return s;
}

__global__ void __launch_bounds__(256)
vloss_main(const float* __restrict__ pred,
           const float* __restrict__ tru,
           float* __restrict__ out,
           int n4, float inv_scale) {
    const float4* p4 = reinterpret_cast<const float4*>(pred);
    const float4* t4 = reinterpret_cast<const float4*>(tru);

    float acc = 0.0f;
    const int tid    = blockIdx.x * blockDim.x + threadIdx.x;
    const int stride = gridDim.x * blockDim.x;

    // Unrolled-by-4 main loop: 8 independent LDG.128 front-batched per iter.
    int i = tid;
    const int stride4 = stride * 4;
    for (; i + 3 * stride < n4; i += stride4) {
        float4 pa = ld4(p4 + i);
        float4 pb = ld4(p4 + i + stride);
        float4 pc = ld4(p4 + i + 2 * stride);
        float4 pd = ld4(p4 + i + 3 * stride);
        float4 ta = ld4(t4 + i);
        float4 tb = ld4(t4 + i + stride);
        float4 tc = ld4(t4 + i + 2 * stride);
        float4 td = ld4(t4 + i + 3 * stride);

        acc -= bce4_lg2(pa, ta);
        acc -= bce4_lg2(pb, tb);
        acc -= bce4_lg2(pc, tc);
        acc -= bce4_lg2(pd, td);
    }
    // Remainder
    for (; i < n4; i += stride) {
        float4 p = ld4(p4 + i);
        float4 t = ld4(t4 + i);
        acc -= bce4_lg2(p, t);
    }

    // warp reduce
    #pragma unroll
    for (int off = 16; off > 0; off >>= 1)
        acc += __shfl_down_sync(0xFFFFFFFFu, acc, off);

    __shared__ float warp_sums[8];
    int lane = threadIdx.x & 31;
    int wid  = threadIdx.x >> 5;
    if (lane == 0) warp_sums[wid] = acc;
    __syncthreads();

    if (wid == 0 && lane == 0) {
        float v = 0.0f;
        #pragma unroll
        for (int w = 0; w < 8; w++) v += warp_sums[w];

        // Accumulate block partial into device-global scalar.
        atomicAdd(&g_acc, v);
        __threadfence();

        // Ticket: last block finalizes the output and resets state so the
        // next graph replay starts clean.
        unsigned int ticket = atomicAdd(&g_count, 1u);
        if (ticket == gridDim.x - 1) {
            *out = g_acc * inv_scale;
            g_acc   = 0.0f;
            g_count = 0u;
        }
    }
}

extern "C" void kernel_launch(void* const* d_in, const int* in_sizes, int n_in,
                              void* d_out, int out_size) {
    const float* pred = (const float*)d_in[0];
    const float* tru  = (const float*)d_in[1];
    float* out = (float*)d_out;

    int n = in_sizes[0];               // 33,554,432
    int n4 = n >> 2;
    // divisor: H * B = 65536 * 64; multiply by ln2 to convert log2 -> ln
    float inv_scale = LN2 / (65536.0f * 64.0f);

    int threads = 256;
    int blocks = 148 * 16;             // 2368 blocks: measured-best concurrency
    vloss_main<<<blocks, threads>>>(pred, tru, out, n4, inv_scale);
}